// round 15
// baseline (speedup 1.0000x reference)
#include <cuda_runtime.h>
#include <cuda_fp16.h>
#include <math.h>
#include <stdint.h>

// Problem constants
#define BB   32
#define LL   256
#define SS   4
#define DD   512
#define HH   1024      // L*S
#define TGBB 128
#define KD1  2560      // 5*D
#define ND1  2048      // 4*D
#define ND2  512       // D
#define MAXM (BB*HH)   // 32768
#define MSPLIT 64      // m-block split for GEMM1/GEMM2 pipelining (rows 0..8191)

#define STATES_ELEMS ((size_t)BB*SS*LL*DD)   // 16777216
#define MASK_ELEMS   ((size_t)BB*SS*LL)      // 32768

// Scratch (device globals; no runtime allocation)
__device__ __align__(128) __half g_x[(size_t)MAXM * KD1];
__device__ __align__(128) __half g_h[(size_t)MAXM * ND1];
__device__ __align__(128) __half g_w1t[(size_t)ND1 * KD1];
__device__ __align__(128) __half g_w2t[(size_t)ND2 * ND1];
__device__ int   g_src[MAXM];
__device__ int   g_dst[MAXM];
__device__ int   g_count;
__device__ int   g_kept[BB * SS];
__device__ int   g_emptyf[BB * SS];

// ---------------------------------------------------------------------------
// Helpers
// ---------------------------------------------------------------------------
__device__ __forceinline__ uint32_t smem_u32(const void* p) {
    uint32_t a;
    asm("{ .reg .u64 t; cvta.to.shared.u64 t, %1; cvt.u32.u64 %0, t; }" : "=r"(a) : "l"(p));
    return a;
}
__device__ __forceinline__ void cpasync16(uint32_t dst, const void* src) {
    asm volatile("cp.async.cg.shared.global [%0], [%1], 16;\n" :: "r"(dst), "l"(src));
}
#define CP_COMMIT() asm volatile("cp.async.commit_group;\n" ::: "memory")
#define CP_WAIT2()  asm volatile("cp.async.wait_group 2;\n" ::: "memory")

__device__ __forceinline__ void mma_f16(float* c, const uint32_t* a, const uint32_t* b) {
    asm volatile(
        "mma.sync.aligned.m16n8k16.row.col.f32.f16.f16.f32 "
        "{%0,%1,%2,%3}, {%4,%5,%6,%7}, {%8,%9}, {%0,%1,%2,%3};"
        : "+f"(c[0]), "+f"(c[1]), "+f"(c[2]), "+f"(c[3])
        : "r"(a[0]), "r"(a[1]), "r"(a[2]), "r"(a[3]), "r"(b[0]), "r"(b[1]));
}
__device__ __forceinline__ void ldsm_x4(uint32_t* r, uint32_t addr) {
    asm volatile("ldmatrix.sync.aligned.m8n8.x4.shared.b16 {%0,%1,%2,%3}, [%4];"
        : "=r"(r[0]), "=r"(r[1]), "=r"(r[2]), "=r"(r[3]) : "r"(addr));
}
__device__ __forceinline__ float silu_fast(float x) {
    return x / (1.0f + __expf(-x));
}

// ---------------------------------------------------------------------------
// Per-batch bucketization
// ---------------------------------------------------------------------------
__global__ void k_build(const int* __restrict__ gids, const int* __restrict__ lengths) {
    int b = blockIdx.x;
    int h = threadIdx.x;
    int len = lengths[b];
    int g = (h < len) ? gids[b * HH + h] : 0;

    unsigned long long v = (g > 0) ? (1ULL << ((g - 1) * 16)) : 0ULL;
    int lane = h & 31, wid = h >> 5;
    #pragma unroll
    for (int o = 1; o < 32; o <<= 1) {
        unsigned long long n = __shfl_up_sync(0xffffffffu, v, o);
        if (lane >= o) v += n;
    }
    __shared__ unsigned long long warpsum[32];
    if (lane == 31) warpsum[wid] = v;
    __syncthreads();
    if (wid == 0) {
        unsigned long long w = warpsum[lane];
        #pragma unroll
        for (int o = 1; o < 32; o <<= 1) {
            unsigned long long n = __shfl_up_sync(0xffffffffu, w, o);
            if (lane >= o) w += n;
        }
        warpsum[lane] = w;
    }
    __syncthreads();
    unsigned long long incl = v + (wid > 0 ? warpsum[wid - 1] : 0ULL);

    __shared__ unsigned long long s_total;
    if (h == HH - 1) s_total = incl;
    __syncthreads();
    unsigned long long tot = s_total;

    if (g > 0) {
        int rank0 = (int)((incl >> ((g - 1) * 16)) & 0xFFFF) - 1;
        int cnt   = (int)((tot  >> ((g - 1) * 16)) & 0xFFFF);
        int off = cnt - LL; if (off < 0) off = 0;
        if (rank0 >= off) {
            int m = atomicAdd(&g_count, 1);
            g_src[m] = b * HH + h;
            g_dst[m] = (b * SS + (g - 1)) * LL + (rank0 - off);
        }
    }
    if (h < SS) {
        int cnt = (int)((tot >> (h * 16)) & 0xFFFF);
        int kept = (cnt == 0) ? 1 : (cnt < LL ? cnt : LL);
        g_kept[b * SS + h] = kept;
        g_emptyf[b * SS + h] = (cnt == 0) ? 1 : 0;
    }
}

// ---------------------------------------------------------------------------
// Output base init + mask: 128 threads, 4 consecutive rows per block
// ---------------------------------------------------------------------------
__global__ void k_base(const float* __restrict__ pos_emb, const float* __restrict__ seq_emb,
                       const float* __restrict__ empty_tok, float* __restrict__ out,
                       int write_mask) {
    int tid = threadIdx.x;
    int r0 = blockIdx.x * 4;
    #pragma unroll
    for (int q = 0; q < 4; q++) {
        int r = r0 + q;
        int slot = r & (LL - 1);
        int bg = r >> 8;
        int g = bg & (SS - 1);
        int kept = g_kept[bg];

        float4 val = make_float4(0.f, 0.f, 0.f, 0.f);
        if (slot < kept) {
            float4 a = ((const float4*)(pos_emb + (size_t)slot * DD))[tid];
            float4 qv = ((const float4*)(seq_emb + (size_t)(g + 1) * DD))[tid];
            val.x = a.x + qv.x; val.y = a.y + qv.y; val.z = a.z + qv.z; val.w = a.w + qv.w;
            if (slot == 0 && g_emptyf[bg]) {
                float4 e = ((const float4*)(empty_tok + (size_t)g * DD))[tid];
                val.x += e.x; val.y += e.y; val.z += e.z; val.w += e.w;
            }
        }
        ((float4*)out)[(size_t)r * (DD / 4) + tid] = val;
        if (write_mask && tid == 0)
            out[STATES_ELEMS + r] = (slot < kept) ? 1.0f : 0.0f;
    }
}

// ---------------------------------------------------------------------------
// Weight transpose [K,N] -> [N,K], fp16 output
// ---------------------------------------------------------------------------
__global__ void k_transpose(const float* __restrict__ W, __half* __restrict__ Wt, int K, int N) {
    __shared__ float t[32][33];
    int n0 = blockIdx.x * 32, k0 = blockIdx.y * 32;
    int tx = threadIdx.x, ty = threadIdx.y;   // 32 x 8
    #pragma unroll
    for (int j = 0; j < 32; j += 8)
        t[ty + j][tx] = W[(size_t)(k0 + ty + j) * N + n0 + tx];
    __syncthreads();
    #pragma unroll
    for (int j = 0; j < 32; j += 8)
        Wt[(size_t)(n0 + ty + j) * K + k0 + tx] = __float2half_rn(t[tx][ty + j]);
}

// ---------------------------------------------------------------------------
// Gather 5 embeddings + LayerNorm: 128 threads, 5 float4 per thread.
// ---------------------------------------------------------------------------
__global__ void k_gather_ln(const float* __restrict__ embed, const float* __restrict__ tg_emb,
                            const float* __restrict__ gamma, const float* __restrict__ beta,
                            const int* __restrict__ ht, const int* __restrict__ pt,
                            const int* __restrict__ at, const int* __restrict__ ct,
                            const int* __restrict__ tgap) {
    int m = blockIdx.x;
    if (m >= g_count) return;
    __shared__ const float* segs[5];
    __shared__ float s_mean, s_rstd;
    __shared__ float rs[4], rss[4];
    int tid = threadIdx.x;   // 128

    if (tid == 0) {
        int src = g_src[m];
        segs[0] = embed + (size_t)ht[src] * DD;
        segs[1] = embed + (size_t)pt[src] * DD;
        segs[2] = embed + (size_t)at[src] * DD;
        segs[3] = embed + (size_t)ct[src] * DD;
        int tg = tgap[src];
        tg = tg < 0 ? 0 : (tg > TGBB ? TGBB : tg);
        segs[4] = tg_emb + (size_t)tg * DD;
    }
    __syncthreads();

    float4 v[5];
    float s = 0.f, ss = 0.f;
    #pragma unroll
    for (int k = 0; k < 5; k++) {
        v[k] = *(const float4*)(segs[k] + tid * 4);
        s  += v[k].x + v[k].y + v[k].z + v[k].w;
        ss += v[k].x * v[k].x + v[k].y * v[k].y + v[k].z * v[k].z + v[k].w * v[k].w;
    }
    #pragma unroll
    for (int o = 16; o > 0; o >>= 1) {
        s  += __shfl_down_sync(0xffffffffu, s,  o);
        ss += __shfl_down_sync(0xffffffffu, ss, o);
    }
    if ((tid & 31) == 0) { rs[tid >> 5] = s; rss[tid >> 5] = ss; }
    __syncthreads();
    if (tid == 0) {
        float S1 = rs[0] + rs[1] + rs[2] + rs[3];
        float S2 = rss[0] + rss[1] + rss[2] + rss[3];
        float mean = S1 * (1.0f / (float)KD1);
        float var = S2 * (1.0f / (float)KD1) - mean * mean;
        s_mean = mean;
        s_rstd = rsqrtf(var + 1e-5f);
    }
    __syncthreads();
    float mean = s_mean, rstd = s_rstd;
    size_t base = (size_t)m * KD1;
    #pragma unroll
    for (int k = 0; k < 5; k++) {
        int j = k * 512 + tid * 4;
        float4 gm = *(const float4*)(gamma + j);
        float4 bt = *(const float4*)(beta + j);
        float x0 = (v[k].x - mean) * rstd * gm.x + bt.x;
        float x1 = (v[k].y - mean) * rstd * gm.y + bt.y;
        float x2 = (v[k].z - mean) * rstd * gm.z + bt.z;
        float x3 = (v[k].w - mean) * rstd * gm.w + bt.w;
        half2 h0 = __floats2half2_rn(x0, x1);
        half2 h1 = __floats2half2_rn(x2, x3);
        *(uint2*)&g_x[base + j] = make_uint2(*(uint32_t*)&h0, *(uint32_t*)&h1);
    }
}

// ---------------------------------------------------------------------------
// FP16 mma.sync GEMM: CTA tile 128x128, K-chunk 64, 3-stage cp.async,
// ldmatrix.x4 fragments, row pitch 72 halves (conflict-free).
// ---------------------------------------------------------------------------
#define ROWP      72
#define ROWB      (ROWP * 2)                // 144 bytes
#define TILE_A    (128 * ROWB)              // 18432
#define STG       (TILE_A * 2)              // 36864
#define GS_BYTES  (3 * STG)                 // 110592

// GEMM1: g_h = fp16(silu(g_x @ w1 + b1))   K=2560, N=2048. m-block = blockIdx.y + yOff.
__global__ void __launch_bounds__(256, 2)
k_mma0(const __half* __restrict__ Bt, const float* __restrict__ bias, int yOff) {
    constexpr int K  = KD1;
    constexpr int NC = K / 64;

    const int count = g_count;
    const int m0 = (blockIdx.y + yOff) * 128;
    if (m0 >= count) return;
    const int n0 = blockIdx.x * 128;

    extern __shared__ __align__(16) char smc[];
    const uint32_t sb = smem_u32(smc);
    const int tid = threadIdx.x;
    const int wid = tid >> 5, lane = tid & 31;
    const int wm = wid & 1, wn = wid >> 1;
    const int g = lane >> 2, tig = lane & 3;
    const int mclamp = count - 1;

    const uint32_t aLane = (uint32_t)(lane & 15) * ROWB + ((lane >> 4) << 3) * 2;
    const uint32_t bLane = (uint32_t)(((lane >> 4) << 3) + (lane & 7)) * ROWB
                         + (((lane >> 3) & 1) << 3) * 2;

    float acc[4][4][4];
    #pragma unroll
    for (int mt = 0; mt < 4; mt++)
        #pragma unroll
        for (int nt = 0; nt < 4; nt++)
            #pragma unroll
            for (int q = 0; q < 4; q++) acc[mt][nt][q] = 0.f;

    auto load_chunk = [&](int c, int st) {
        int kc = c * 64;
        uint32_t aB = sb + st * STG;
        uint32_t bB = aB + TILE_A;
        int id = tid;
        #pragma unroll
        for (int j = 0; j < 4; j++) {
            int r = id >> 3, cc = id & 7;
            int gr = m0 + r; gr = gr > mclamp ? mclamp : gr;
            cpasync16(aB + r * ROWB + cc * 16, g_x + (size_t)gr * K + kc + cc * 8);
            id += 256;
        }
        id = tid;
        #pragma unroll
        for (int j = 0; j < 4; j++) {
            int r = id >> 3, cc = id & 7;
            cpasync16(bB + r * ROWB + cc * 16, Bt + (size_t)(n0 + r) * K + kc + cc * 8);
            id += 256;
        }
    };

    #pragma unroll
    for (int c = 0; c < 3; c++) { load_chunk(c, c); CP_COMMIT(); }

    int stage = 0;
    for (int i = 0; i < NC; i++) {
        CP_WAIT2();
        __syncthreads();

        uint32_t aS = sb + stage * STG;
        uint32_t bS = aS + TILE_A;

        #pragma unroll
        for (int ks = 0; ks < 4; ks++) {
            uint32_t kOff = ks * 32;
            uint32_t afr[4][4];
            uint32_t bfr[2][4];
            #pragma unroll
            for (int mt = 0; mt < 4; mt++)
                ldsm_x4(afr[mt], aS + (uint32_t)(wm * 64 + mt * 16) * ROWB + aLane + kOff);
            #pragma unroll
            for (int p = 0; p < 2; p++)
                ldsm_x4(bfr[p], bS + (uint32_t)(wn * 32 + p * 16) * ROWB + bLane + kOff);
            #pragma unroll
            for (int mt = 0; mt < 4; mt++) {
                #pragma unroll
                for (int p = 0; p < 2; p++) {
                    mma_f16(acc[mt][2 * p],     afr[mt], &bfr[p][0]);
                    mma_f16(acc[mt][2 * p + 1], afr[mt], &bfr[p][2]);
                }
            }
        }
        __syncthreads();
        if (i + 3 < NC) load_chunk(i + 3, stage);
        CP_COMMIT();
        stage = (stage == 2) ? 0 : stage + 1;
    }

    #pragma unroll
    for (int mt = 0; mt < 4; mt++) {
        int r1 = m0 + wm * 64 + mt * 16 + g;
        int r2 = r1 + 8;
        bool v1 = r1 < count, v2 = r2 < count;
        #pragma unroll
        for (int nt = 0; nt < 4; nt++) {
            int c = n0 + wn * 32 + nt * 8 + tig * 2;
            float bx = __ldg(&bias[c]), by = __ldg(&bias[c + 1]);
            if (v1) {
                float x = silu_fast(acc[mt][nt][0] + bx);
                float y = silu_fast(acc[mt][nt][1] + by);
                *(half2*)&g_h[(size_t)r1 * ND1 + c] = __floats2half2_rn(x, y);
            }
            if (v2) {
                float x = silu_fast(acc[mt][nt][2] + bx);
                float y = silu_fast(acc[mt][nt][3] + by);
                *(half2*)&g_h[(size_t)r2 * ND1 + c] = __floats2half2_rn(x, y);
            }
        }
    }
}

// GEMM2 split-K=2: out[g_dst[m]] += (g_h @ w2)[k-half] (+ b2 on z==0), via atomicAdd.
// m-block = blockIdx.y + yOff (range-split launches).
__global__ void __launch_bounds__(256, 2)
k_mma1(const __half* __restrict__ Bt, const float* __restrict__ bias, float* __restrict__ out,
       int yOff) {
    constexpr int KH = ND1 / 2;      // 1024 per K-half
    constexpr int NC = KH / 64;      // 16 chunks

    const int count = g_count;
    const int m0 = (blockIdx.y + yOff) * 128;
    if (m0 >= count) return;
    const int n0 = blockIdx.x * 128;
    const int kbase = blockIdx.z * KH;
    const bool addBias = (blockIdx.z == 0);

    extern __shared__ __align__(16) char smc[];
    const uint32_t sb = smem_u32(smc);
    const int tid = threadIdx.x;
    const int wid = tid >> 5, lane = tid & 31;
    const int wm = wid & 1, wn = wid >> 1;
    const int g = lane >> 2, tig = lane & 3;
    const int mclamp = count - 1;

    const uint32_t aLane = (uint32_t)(lane & 15) * ROWB + ((lane >> 4) << 3) * 2;
    const uint32_t bLane = (uint32_t)(((lane >> 4) << 3) + (lane & 7)) * ROWB
                         + (((lane >> 3) & 1) << 3) * 2;

    float acc[4][4][4];
    #pragma unroll
    for (int mt = 0; mt < 4; mt++)
        #pragma unroll
        for (int nt = 0; nt < 4; nt++)
            #pragma unroll
            for (int q = 0; q < 4; q++) acc[mt][nt][q] = 0.f;

    auto load_chunk = [&](int c, int st) {
        int kc = kbase + c * 64;
        uint32_t aB = sb + st * STG;
        uint32_t bB = aB + TILE_A;
        int id = tid;
        #pragma unroll
        for (int j = 0; j < 4; j++) {
            int r = id >> 3, cc = id & 7;
            int gr = m0 + r; gr = gr > mclamp ? mclamp : gr;
            cpasync16(aB + r * ROWB + cc * 16, g_h + (size_t)gr * ND1 + kc + cc * 8);
            id += 256;
        }
        id = tid;
        #pragma unroll
        for (int j = 0; j < 4; j++) {
            int r = id >> 3, cc = id & 7;
            cpasync16(bB + r * ROWB + cc * 16, Bt + (size_t)(n0 + r) * ND1 + kc + cc * 8);
            id += 256;
        }
    };

    #pragma unroll
    for (int c = 0; c < 3; c++) { load_chunk(c, c); CP_COMMIT(); }

    int stage = 0;
    for (int i = 0; i < NC; i++) {
        CP_WAIT2();
        __syncthreads();

        uint32_t aS = sb + stage * STG;
        uint32_t bS = aS + TILE_A;

        #pragma unroll
        for (int ks = 0; ks < 4; ks++) {
            uint32_t kOff = ks * 32;
            uint32_t afr[4][4];
            uint32_t bfr[2][4];
            #pragma unroll
            for (int mt = 0; mt < 4; mt++)
                ldsm_x4(afr[mt], aS + (uint32_t)(wm * 64 + mt * 16) * ROWB + aLane + kOff);
            #pragma unroll
            for (int p = 0; p < 2; p++)
                ldsm_x4(bfr[p], bS + (uint32_t)(wn * 32 + p * 16) * ROWB + bLane + kOff);
            #pragma unroll
            for (int mt = 0; mt < 4; mt++) {
                #pragma unroll
                for (int p = 0; p < 2; p++) {
                    mma_f16(acc[mt][2 * p],     afr[mt], &bfr[p][0]);
                    mma_f16(acc[mt][2 * p + 1], afr[mt], &bfr[p][2]);
                }
            }
        }
        __syncthreads();
        if (i + 3 < NC) load_chunk(i + 3, stage);
        CP_COMMIT();
        stage = (stage == 2) ? 0 : stage + 1;
    }

    // ---- epilogue: atomic scatter accumulate ----
    #pragma unroll
    for (int mt = 0; mt < 4; mt++) {
        int r1 = m0 + wm * 64 + mt * 16 + g;
        int r2 = r1 + 8;
        bool v1 = r1 < count, v2 = r2 < count;
        int d1 = v1 ? g_dst[r1] : 0;
        int d2 = v2 ? g_dst[r2] : 0;
        #pragma unroll
        for (int nt = 0; nt < 4; nt++) {
            int c = n0 + wn * 32 + nt * 8 + tig * 2;
            float bx = addBias ? __ldg(&bias[c]) : 0.f;
            float by = addBias ? __ldg(&bias[c + 1]) : 0.f;
            if (v1) {
                float* p = &out[(size_t)d1 * ND2 + c];
                atomicAdd(p,     acc[mt][nt][0] + bx);
                atomicAdd(p + 1, acc[mt][nt][1] + by);
            }
            if (v2) {
                float* p = &out[(size_t)d2 * ND2 + c];
                atomicAdd(p,     acc[mt][nt][2] + bx);
                atomicAdd(p + 1, acc[mt][nt][3] + by);
            }
        }
    }
}

// ---------------------------------------------------------------------------
extern "C" void kernel_launch(void* const* d_in, const int* in_sizes, int n_in,
                              void* d_out, int out_size) {
    const float* embed     = (const float*)d_in[0];
    const float* tg_emb    = (const float*)d_in[1];
    const float* seq_emb   = (const float*)d_in[2];
    const float* pos_emb   = (const float*)d_in[3];
    const float* gamma     = (const float*)d_in[4];
    const float* beta      = (const float*)d_in[5];
    const float* w1        = (const float*)d_in[6];
    const float* b1        = (const float*)d_in[7];
    const float* w2        = (const float*)d_in[8];
    const float* b2        = (const float*)d_in[9];
    const float* empty_tok = (const float*)d_in[10];
    const int*   ht        = (const int*)d_in[11];
    const int*   pt        = (const int*)d_in[12];
    const int*   at        = (const int*)d_in[13];
    const int*   ct        = (const int*)d_in[14];
    const int*   tgap      = (const int*)d_in[15];
    const int*   gids      = (const int*)d_in[16];
    const int*   lengths   = (const int*)d_in[17];
    float* out = (float*)d_out;

    int write_mask = ((size_t)out_size >= STATES_ELEMS + MASK_ELEMS) ? 1 : 0;

    __half* w1t_p; cudaGetSymbolAddress((void**)&w1t_p, g_w1t);
    __half* w2t_p; cudaGetSymbolAddress((void**)&w2t_p, g_w2t);
    int* cnt_p;    cudaGetSymbolAddress((void**)&cnt_p, g_count);

    static cudaStream_t s1 = nullptr, s2 = nullptr;
    static cudaEvent_t evFork = nullptr, evBuild = nullptr, evT1 = nullptr,
                       evSide = nullptr, evG = nullptr, evB = nullptr;
    if (!s1) {
        cudaStreamCreateWithFlags(&s1, cudaStreamNonBlocking);
        cudaStreamCreateWithFlags(&s2, cudaStreamNonBlocking);
        cudaEventCreateWithFlags(&evFork,  cudaEventDisableTiming);
        cudaEventCreateWithFlags(&evBuild, cudaEventDisableTiming);
        cudaEventCreateWithFlags(&evT1,    cudaEventDisableTiming);
        cudaEventCreateWithFlags(&evSide,  cudaEventDisableTiming);
        cudaEventCreateWithFlags(&evG,     cudaEventDisableTiming);
        cudaEventCreateWithFlags(&evB,     cudaEventDisableTiming);
    }

    cudaFuncSetAttribute(k_mma0, cudaFuncAttributeMaxDynamicSharedMemorySize, GS_BYTES);
    cudaFuncSetAttribute(k_mma1, cudaFuncAttributeMaxDynamicSharedMemorySize, GS_BYTES);

    cudaMemsetAsync(cnt_p, 0, sizeof(int), 0);
    cudaEventRecord(evFork, 0);
    cudaStreamWaitEvent(s1, evFork, 0);

    // main stream: build -> gather(all) -> mma0_a -> mma1_a -> mma1_b
    k_build<<<BB, HH>>>(gids, lengths);
    cudaEventRecord(evBuild, 0);

    // s1: w1T -> (evT1) -> w2T -> base(needs build) -> (evSide)
    k_transpose<<<dim3(ND1 / 32, KD1 / 32), dim3(32, 8), 0, s1>>>(w1, w1t_p, KD1, ND1);
    cudaEventRecord(evT1, s1);
    k_transpose<<<dim3(ND2 / 32, ND1 / 32), dim3(32, 8), 0, s1>>>(w2, w2t_p, ND1, ND2);
    cudaStreamWaitEvent(s1, evBuild, 0);
    k_base<<<BB * SS * LL / 4, 128, 0, s1>>>(pos_emb, seq_emb, empty_tok, out, write_mask);
    cudaEventRecord(evSide, s1);

    // main: gather all rows, then GEMM1 first half (m-blocks 0..MSPLIT-1)
    k_gather_ln<<<MAXM, 128>>>(embed, tg_emb, gamma, beta, ht, pt, at, ct, tgap);
    cudaEventRecord(evG, 0);
    cudaStreamWaitEvent(0, evT1, 0);
    k_mma0<<<dim3(ND1 / 128, MSPLIT), 256, GS_BYTES>>>(w1t_p, b1, 0);

    // s2: GEMM1 second half (m-blocks MSPLIT..255) — concurrent with mma0_a
    cudaStreamWaitEvent(s2, evG, 0);
    cudaStreamWaitEvent(s2, evT1, 0);
    k_mma0<<<dim3(ND1 / 128, MAXM / 128 - MSPLIT), 256, GS_BYTES, s2>>>(w1t_p, b1, MSPLIT);
    cudaEventRecord(evB, s2);

    // main: GEMM2 first half (m 0..MSPLIT-1) — needs mma0_a (stream order) + base;
    // fills GEMM1's tail while mma0_b drains on s2.
    cudaStreamWaitEvent(0, evSide, 0);
    k_mma1<<<dim3(ND2 / 128, MSPLIT, 2), 256, GS_BYTES>>>(w2t_p, b2, out, 0);

    // main: GEMM2 second half after mma0_b completes
    cudaStreamWaitEvent(0, evB, 0);
    k_mma1<<<dim3(ND2 / 128, MAXM / 128 - MSPLIT, 2), 256, GS_BYTES>>>(w2t_p, b2, out, MSPLIT);
}

// round 16
// speedup vs baseline: 1.0399x; 1.0399x over previous
#include <cuda_runtime.h>
#include <cuda_fp16.h>
#include <math.h>
#include <stdint.h>

// Problem constants
#define BB   32
#define LL   256
#define SS   4
#define DD   512
#define HH   1024      // L*S
#define TGBB 128
#define KD1  2560      // 5*D
#define ND1  2048      // 4*D
#define ND2  512       // D
#define MAXM (BB*HH)   // 32768

#define STATES_ELEMS ((size_t)BB*SS*LL*DD)   // 16777216
#define MASK_ELEMS   ((size_t)BB*SS*LL)      // 32768

// Scratch (device globals; no runtime allocation)
__device__ __align__(128) __half g_x[(size_t)MAXM * KD1];
__device__ __align__(128) __half g_h[(size_t)MAXM * ND1];
__device__ __align__(128) __half g_w1t[(size_t)ND1 * KD1];
__device__ __align__(128) __half g_w2t[(size_t)ND2 * ND1];
__device__ int   g_src[MAXM];
__device__ int   g_dst[MAXM];
__device__ int   g_count;
__device__ int   g_kept[BB * SS];
__device__ int   g_emptyf[BB * SS];

// ---------------------------------------------------------------------------
// Helpers
// ---------------------------------------------------------------------------
__device__ __forceinline__ uint32_t smem_u32(const void* p) {
    uint32_t a;
    asm("{ .reg .u64 t; cvta.to.shared.u64 t, %1; cvt.u32.u64 %0, t; }" : "=r"(a) : "l"(p));
    return a;
}
__device__ __forceinline__ void cpasync16(uint32_t dst, const void* src) {
    asm volatile("cp.async.cg.shared.global [%0], [%1], 16;\n" :: "r"(dst), "l"(src));
}
#define CP_COMMIT() asm volatile("cp.async.commit_group;\n" ::: "memory")
#define CP_WAIT2()  asm volatile("cp.async.wait_group 2;\n" ::: "memory")

__device__ __forceinline__ void mma_f16(float* c, const uint32_t* a, const uint32_t* b) {
    asm volatile(
        "mma.sync.aligned.m16n8k16.row.col.f32.f16.f16.f32 "
        "{%0,%1,%2,%3}, {%4,%5,%6,%7}, {%8,%9}, {%0,%1,%2,%3};"
        : "+f"(c[0]), "+f"(c[1]), "+f"(c[2]), "+f"(c[3])
        : "r"(a[0]), "r"(a[1]), "r"(a[2]), "r"(a[3]), "r"(b[0]), "r"(b[1]));
}
__device__ __forceinline__ void ldsm_x4(uint32_t* r, uint32_t addr) {
    asm volatile("ldmatrix.sync.aligned.m8n8.x4.shared.b16 {%0,%1,%2,%3}, [%4];"
        : "=r"(r[0]), "=r"(r[1]), "=r"(r[2]), "=r"(r[3]) : "r"(addr));
}
__device__ __forceinline__ float silu_fast(float x) {
    return x / (1.0f + __expf(-x));
}

// ---------------------------------------------------------------------------
// Per-batch bucketization
// ---------------------------------------------------------------------------
__global__ void k_build(const int* __restrict__ gids, const int* __restrict__ lengths) {
    int b = blockIdx.x;
    int h = threadIdx.x;
    int len = lengths[b];
    int g = (h < len) ? gids[b * HH + h] : 0;

    unsigned long long v = (g > 0) ? (1ULL << ((g - 1) * 16)) : 0ULL;
    int lane = h & 31, wid = h >> 5;
    #pragma unroll
    for (int o = 1; o < 32; o <<= 1) {
        unsigned long long n = __shfl_up_sync(0xffffffffu, v, o);
        if (lane >= o) v += n;
    }
    __shared__ unsigned long long warpsum[32];
    if (lane == 31) warpsum[wid] = v;
    __syncthreads();
    if (wid == 0) {
        unsigned long long w = warpsum[lane];
        #pragma unroll
        for (int o = 1; o < 32; o <<= 1) {
            unsigned long long n = __shfl_up_sync(0xffffffffu, w, o);
            if (lane >= o) w += n;
        }
        warpsum[lane] = w;
    }
    __syncthreads();
    unsigned long long incl = v + (wid > 0 ? warpsum[wid - 1] : 0ULL);

    __shared__ unsigned long long s_total;
    if (h == HH - 1) s_total = incl;
    __syncthreads();
    unsigned long long tot = s_total;

    if (g > 0) {
        int rank0 = (int)((incl >> ((g - 1) * 16)) & 0xFFFF) - 1;
        int cnt   = (int)((tot  >> ((g - 1) * 16)) & 0xFFFF);
        int off = cnt - LL; if (off < 0) off = 0;
        if (rank0 >= off) {
            int m = atomicAdd(&g_count, 1);
            g_src[m] = b * HH + h;
            g_dst[m] = (b * SS + (g - 1)) * LL + (rank0 - off);
        }
    }
    if (h < SS) {
        int cnt = (int)((tot >> (h * 16)) & 0xFFFF);
        int kept = (cnt == 0) ? 1 : (cnt < LL ? cnt : LL);
        g_kept[b * SS + h] = kept;
        g_emptyf[b * SS + h] = (cnt == 0) ? 1 : 0;
    }
}

// ---------------------------------------------------------------------------
// Output base init + mask: 128 threads, 4 consecutive rows per block
// ---------------------------------------------------------------------------
__global__ void k_base(const float* __restrict__ pos_emb, const float* __restrict__ seq_emb,
                       const float* __restrict__ empty_tok, float* __restrict__ out,
                       int write_mask) {
    int tid = threadIdx.x;
    int r0 = blockIdx.x * 4;
    #pragma unroll
    for (int q = 0; q < 4; q++) {
        int r = r0 + q;
        int slot = r & (LL - 1);
        int bg = r >> 8;
        int g = bg & (SS - 1);
        int kept = g_kept[bg];

        float4 val = make_float4(0.f, 0.f, 0.f, 0.f);
        if (slot < kept) {
            float4 a = ((const float4*)(pos_emb + (size_t)slot * DD))[tid];
            float4 qv = ((const float4*)(seq_emb + (size_t)(g + 1) * DD))[tid];
            val.x = a.x + qv.x; val.y = a.y + qv.y; val.z = a.z + qv.z; val.w = a.w + qv.w;
            if (slot == 0 && g_emptyf[bg]) {
                float4 e = ((const float4*)(empty_tok + (size_t)g * DD))[tid];
                val.x += e.x; val.y += e.y; val.z += e.z; val.w += e.w;
            }
        }
        ((float4*)out)[(size_t)r * (DD / 4) + tid] = val;
        if (write_mask && tid == 0)
            out[STATES_ELEMS + r] = (slot < kept) ? 1.0f : 0.0f;
    }
}

// ---------------------------------------------------------------------------
// Weight transpose [K,N] -> [N,K], fp16 output
// ---------------------------------------------------------------------------
__global__ void k_transpose(const float* __restrict__ W, __half* __restrict__ Wt, int K, int N) {
    __shared__ float t[32][33];
    int n0 = blockIdx.x * 32, k0 = blockIdx.y * 32;
    int tx = threadIdx.x, ty = threadIdx.y;   // 32 x 8
    #pragma unroll
    for (int j = 0; j < 32; j += 8)
        t[ty + j][tx] = W[(size_t)(k0 + ty + j) * N + n0 + tx];
    __syncthreads();
    #pragma unroll
    for (int j = 0; j < 32; j += 8)
        Wt[(size_t)(n0 + ty + j) * K + k0 + tx] = __float2half_rn(t[tx][ty + j]);
}

// ---------------------------------------------------------------------------
// Gather 5 embeddings + LayerNorm: 128 threads, 5 float4 per thread.
// ---------------------------------------------------------------------------
__global__ void k_gather_ln(const float* __restrict__ embed, const float* __restrict__ tg_emb,
                            const float* __restrict__ gamma, const float* __restrict__ beta,
                            const int* __restrict__ ht, const int* __restrict__ pt,
                            const int* __restrict__ at, const int* __restrict__ ct,
                            const int* __restrict__ tgap) {
    int m = blockIdx.x;
    if (m >= g_count) return;
    __shared__ const float* segs[5];
    __shared__ float s_mean, s_rstd;
    __shared__ float rs[4], rss[4];
    int tid = threadIdx.x;   // 128

    if (tid == 0) {
        int src = g_src[m];
        segs[0] = embed + (size_t)ht[src] * DD;
        segs[1] = embed + (size_t)pt[src] * DD;
        segs[2] = embed + (size_t)at[src] * DD;
        segs[3] = embed + (size_t)ct[src] * DD;
        int tg = tgap[src];
        tg = tg < 0 ? 0 : (tg > TGBB ? TGBB : tg);
        segs[4] = tg_emb + (size_t)tg * DD;
    }
    __syncthreads();

    float4 v[5];
    float s = 0.f, ss = 0.f;
    #pragma unroll
    for (int k = 0; k < 5; k++) {
        v[k] = *(const float4*)(segs[k] + tid * 4);
        s  += v[k].x + v[k].y + v[k].z + v[k].w;
        ss += v[k].x * v[k].x + v[k].y * v[k].y + v[k].z * v[k].z + v[k].w * v[k].w;
    }
    #pragma unroll
    for (int o = 16; o > 0; o >>= 1) {
        s  += __shfl_down_sync(0xffffffffu, s,  o);
        ss += __shfl_down_sync(0xffffffffu, ss, o);
    }
    if ((tid & 31) == 0) { rs[tid >> 5] = s; rss[tid >> 5] = ss; }
    __syncthreads();
    if (tid == 0) {
        float S1 = rs[0] + rs[1] + rs[2] + rs[3];
        float S2 = rss[0] + rss[1] + rss[2] + rss[3];
        float mean = S1 * (1.0f / (float)KD1);
        float var = S2 * (1.0f / (float)KD1) - mean * mean;
        s_mean = mean;
        s_rstd = rsqrtf(var + 1e-5f);
    }
    __syncthreads();
    float mean = s_mean, rstd = s_rstd;
    size_t base = (size_t)m * KD1;
    #pragma unroll
    for (int k = 0; k < 5; k++) {
        int j = k * 512 + tid * 4;
        float4 gm = *(const float4*)(gamma + j);
        float4 bt = *(const float4*)(beta + j);
        float x0 = (v[k].x - mean) * rstd * gm.x + bt.x;
        float x1 = (v[k].y - mean) * rstd * gm.y + bt.y;
        float x2 = (v[k].z - mean) * rstd * gm.z + bt.z;
        float x3 = (v[k].w - mean) * rstd * gm.w + bt.w;
        half2 h0 = __floats2half2_rn(x0, x1);
        half2 h1 = __floats2half2_rn(x2, x3);
        *(uint2*)&g_x[base + j] = make_uint2(*(uint32_t*)&h0, *(uint32_t*)&h1);
    }
}

// ---------------------------------------------------------------------------
// FP16 mma.sync GEMM: CTA tile 128x128, K-chunk 64, 3-stage cp.async,
// ldmatrix.x4 fragments, row pitch 72 halves (conflict-free).
// ---------------------------------------------------------------------------
#define ROWP      72
#define ROWB      (ROWP * 2)                // 144 bytes
#define TILE_A    (128 * ROWB)              // 18432
#define STG       (TILE_A * 2)              // 36864
#define GS_BYTES  (3 * STG)                 // 110592

// GEMM1: g_h = fp16(silu(g_x @ w1 + b1))   K=2560, N=2048
__global__ void __launch_bounds__(256, 2)
k_mma0(const __half* __restrict__ Bt, const float* __restrict__ bias) {
    constexpr int K  = KD1;
    constexpr int NC = K / 64;

    const int count = g_count;
    const int m0 = blockIdx.y * 128;
    if (m0 >= count) return;
    const int n0 = blockIdx.x * 128;

    extern __shared__ __align__(16) char smc[];
    const uint32_t sb = smem_u32(smc);
    const int tid = threadIdx.x;
    const int wid = tid >> 5, lane = tid & 31;
    const int wm = wid & 1, wn = wid >> 1;
    const int g = lane >> 2, tig = lane & 3;
    const int mclamp = count - 1;

    const uint32_t aLane = (uint32_t)(lane & 15) * ROWB + ((lane >> 4) << 3) * 2;
    const uint32_t bLane = (uint32_t)(((lane >> 4) << 3) + (lane & 7)) * ROWB
                         + (((lane >> 3) & 1) << 3) * 2;

    float acc[4][4][4];
    #pragma unroll
    for (int mt = 0; mt < 4; mt++)
        #pragma unroll
        for (int nt = 0; nt < 4; nt++)
            #pragma unroll
            for (int q = 0; q < 4; q++) acc[mt][nt][q] = 0.f;

    auto load_chunk = [&](int c, int st) {
        int kc = c * 64;
        uint32_t aB = sb + st * STG;
        uint32_t bB = aB + TILE_A;
        int id = tid;
        #pragma unroll
        for (int j = 0; j < 4; j++) {
            int r = id >> 3, cc = id & 7;
            int gr = m0 + r; gr = gr > mclamp ? mclamp : gr;
            cpasync16(aB + r * ROWB + cc * 16, g_x + (size_t)gr * K + kc + cc * 8);
            id += 256;
        }
        id = tid;
        #pragma unroll
        for (int j = 0; j < 4; j++) {
            int r = id >> 3, cc = id & 7;
            cpasync16(bB + r * ROWB + cc * 16, Bt + (size_t)(n0 + r) * K + kc + cc * 8);
            id += 256;
        }
    };

    #pragma unroll
    for (int c = 0; c < 3; c++) { load_chunk(c, c); CP_COMMIT(); }

    int stage = 0;
    for (int i = 0; i < NC; i++) {
        CP_WAIT2();
        __syncthreads();

        uint32_t aS = sb + stage * STG;
        uint32_t bS = aS + TILE_A;

        #pragma unroll
        for (int ks = 0; ks < 4; ks++) {
            uint32_t kOff = ks * 32;
            uint32_t afr[4][4];
            uint32_t bfr[2][4];
            #pragma unroll
            for (int mt = 0; mt < 4; mt++)
                ldsm_x4(afr[mt], aS + (uint32_t)(wm * 64 + mt * 16) * ROWB + aLane + kOff);
            #pragma unroll
            for (int p = 0; p < 2; p++)
                ldsm_x4(bfr[p], bS + (uint32_t)(wn * 32 + p * 16) * ROWB + bLane + kOff);
            #pragma unroll
            for (int mt = 0; mt < 4; mt++) {
                #pragma unroll
                for (int p = 0; p < 2; p++) {
                    mma_f16(acc[mt][2 * p],     afr[mt], &bfr[p][0]);
                    mma_f16(acc[mt][2 * p + 1], afr[mt], &bfr[p][2]);
                }
            }
        }
        __syncthreads();
        if (i + 3 < NC) load_chunk(i + 3, stage);
        CP_COMMIT();
        stage = (stage == 2) ? 0 : stage + 1;
    }

    #pragma unroll
    for (int mt = 0; mt < 4; mt++) {
        int r1 = m0 + wm * 64 + mt * 16 + g;
        int r2 = r1 + 8;
        bool v1 = r1 < count, v2 = r2 < count;
        #pragma unroll
        for (int nt = 0; nt < 4; nt++) {
            int c = n0 + wn * 32 + nt * 8 + tig * 2;
            float bx = __ldg(&bias[c]), by = __ldg(&bias[c + 1]);
            if (v1) {
                float x = silu_fast(acc[mt][nt][0] + bx);
                float y = silu_fast(acc[mt][nt][1] + by);
                *(half2*)&g_h[(size_t)r1 * ND1 + c] = __floats2half2_rn(x, y);
            }
            if (v2) {
                float x = silu_fast(acc[mt][nt][2] + bx);
                float y = silu_fast(acc[mt][nt][3] + by);
                *(half2*)&g_h[(size_t)r2 * ND1 + c] = __floats2half2_rn(x, y);
            }
        }
    }
}

// GEMM2 split-K=2: out[g_dst[m]] += (g_h @ w2)[k-half] (+ b2 on z==0), via atomicAdd.
__global__ void __launch_bounds__(256, 2)
k_mma1(const __half* __restrict__ Bt, const float* __restrict__ bias, float* __restrict__ out) {
    constexpr int KH = ND1 / 2;      // 1024 per K-half
    constexpr int NC = KH / 64;      // 16 chunks

    const int count = g_count;
    const int m0 = blockIdx.y * 128;
    if (m0 >= count) return;
    const int n0 = blockIdx.x * 128;
    const int kbase = blockIdx.z * KH;
    const bool addBias = (blockIdx.z == 0);

    extern __shared__ __align__(16) char smc[];
    const uint32_t sb = smem_u32(smc);
    const int tid = threadIdx.x;
    const int wid = tid >> 5, lane = tid & 31;
    const int wm = wid & 1, wn = wid >> 1;
    const int g = lane >> 2, tig = lane & 3;
    const int mclamp = count - 1;

    const uint32_t aLane = (uint32_t)(lane & 15) * ROWB + ((lane >> 4) << 3) * 2;
    const uint32_t bLane = (uint32_t)(((lane >> 4) << 3) + (lane & 7)) * ROWB
                         + (((lane >> 3) & 1) << 3) * 2;

    float acc[4][4][4];
    #pragma unroll
    for (int mt = 0; mt < 4; mt++)
        #pragma unroll
        for (int nt = 0; nt < 4; nt++)
            #pragma unroll
            for (int q = 0; q < 4; q++) acc[mt][nt][q] = 0.f;

    auto load_chunk = [&](int c, int st) {
        int kc = kbase + c * 64;
        uint32_t aB = sb + st * STG;
        uint32_t bB = aB + TILE_A;
        int id = tid;
        #pragma unroll
        for (int j = 0; j < 4; j++) {
            int r = id >> 3, cc = id & 7;
            int gr = m0 + r; gr = gr > mclamp ? mclamp : gr;
            cpasync16(aB + r * ROWB + cc * 16, g_h + (size_t)gr * ND1 + kc + cc * 8);
            id += 256;
        }
        id = tid;
        #pragma unroll
        for (int j = 0; j < 4; j++) {
            int r = id >> 3, cc = id & 7;
            cpasync16(bB + r * ROWB + cc * 16, Bt + (size_t)(n0 + r) * ND1 + kc + cc * 8);
            id += 256;
        }
    };

    #pragma unroll
    for (int c = 0; c < 3; c++) { load_chunk(c, c); CP_COMMIT(); }

    int stage = 0;
    for (int i = 0; i < NC; i++) {
        CP_WAIT2();
        __syncthreads();

        uint32_t aS = sb + stage * STG;
        uint32_t bS = aS + TILE_A;

        #pragma unroll
        for (int ks = 0; ks < 4; ks++) {
            uint32_t kOff = ks * 32;
            uint32_t afr[4][4];
            uint32_t bfr[2][4];
            #pragma unroll
            for (int mt = 0; mt < 4; mt++)
                ldsm_x4(afr[mt], aS + (uint32_t)(wm * 64 + mt * 16) * ROWB + aLane + kOff);
            #pragma unroll
            for (int p = 0; p < 2; p++)
                ldsm_x4(bfr[p], bS + (uint32_t)(wn * 32 + p * 16) * ROWB + bLane + kOff);
            #pragma unroll
            for (int mt = 0; mt < 4; mt++) {
                #pragma unroll
                for (int p = 0; p < 2; p++) {
                    mma_f16(acc[mt][2 * p],     afr[mt], &bfr[p][0]);
                    mma_f16(acc[mt][2 * p + 1], afr[mt], &bfr[p][2]);
                }
            }
        }
        __syncthreads();
        if (i + 3 < NC) load_chunk(i + 3, stage);
        CP_COMMIT();
        stage = (stage == 2) ? 0 : stage + 1;
    }

    // ---- epilogue: atomic scatter accumulate ----
    #pragma unroll
    for (int mt = 0; mt < 4; mt++) {
        int r1 = m0 + wm * 64 + mt * 16 + g;
        int r2 = r1 + 8;
        bool v1 = r1 < count, v2 = r2 < count;
        int d1 = v1 ? g_dst[r1] : 0;
        int d2 = v2 ? g_dst[r2] : 0;
        #pragma unroll
        for (int nt = 0; nt < 4; nt++) {
            int c = n0 + wn * 32 + nt * 8 + tig * 2;
            float bx = addBias ? __ldg(&bias[c]) : 0.f;
            float by = addBias ? __ldg(&bias[c + 1]) : 0.f;
            if (v1) {
                float* p = &out[(size_t)d1 * ND2 + c];
                atomicAdd(p,     acc[mt][nt][0] + bx);
                atomicAdd(p + 1, acc[mt][nt][1] + by);
            }
            if (v2) {
                float* p = &out[(size_t)d2 * ND2 + c];
                atomicAdd(p,     acc[mt][nt][2] + bx);
                atomicAdd(p + 1, acc[mt][nt][3] + by);
            }
        }
    }
}

// ---------------------------------------------------------------------------
extern "C" void kernel_launch(void* const* d_in, const int* in_sizes, int n_in,
                              void* d_out, int out_size) {
    const float* embed     = (const float*)d_in[0];
    const float* tg_emb    = (const float*)d_in[1];
    const float* seq_emb   = (const float*)d_in[2];
    const float* pos_emb   = (const float*)d_in[3];
    const float* gamma     = (const float*)d_in[4];
    const float* beta      = (const float*)d_in[5];
    const float* w1        = (const float*)d_in[6];
    const float* b1        = (const float*)d_in[7];
    const float* w2        = (const float*)d_in[8];
    const float* b2        = (const float*)d_in[9];
    const float* empty_tok = (const float*)d_in[10];
    const int*   ht        = (const int*)d_in[11];
    const int*   pt        = (const int*)d_in[12];
    const int*   at        = (const int*)d_in[13];
    const int*   ct        = (const int*)d_in[14];
    const int*   tgap      = (const int*)d_in[15];
    const int*   gids      = (const int*)d_in[16];
    const int*   lengths   = (const int*)d_in[17];
    float* out = (float*)d_out;

    int write_mask = ((size_t)out_size >= STATES_ELEMS + MASK_ELEMS) ? 1 : 0;

    __half* w1t_p; cudaGetSymbolAddress((void**)&w1t_p, g_w1t);
    __half* w2t_p; cudaGetSymbolAddress((void**)&w2t_p, g_w2t);
    int* cnt_p;    cudaGetSymbolAddress((void**)&cnt_p, g_count);

    static cudaStream_t s1 = nullptr;
    static cudaEvent_t evFork = nullptr, evBuild = nullptr, evT1 = nullptr, evSide = nullptr;
    if (!s1) {
        cudaStreamCreateWithFlags(&s1, cudaStreamNonBlocking);
        cudaEventCreateWithFlags(&evFork,  cudaEventDisableTiming);
        cudaEventCreateWithFlags(&evBuild, cudaEventDisableTiming);
        cudaEventCreateWithFlags(&evT1,    cudaEventDisableTiming);
        cudaEventCreateWithFlags(&evSide,  cudaEventDisableTiming);
    }

    cudaFuncSetAttribute(k_mma0, cudaFuncAttributeMaxDynamicSharedMemorySize, GS_BYTES);
    cudaFuncSetAttribute(k_mma1, cudaFuncAttributeMaxDynamicSharedMemorySize, GS_BYTES);

    cudaMemsetAsync(cnt_p, 0, sizeof(int), 0);
    cudaEventRecord(evFork, 0);
    cudaStreamWaitEvent(s1, evFork, 0);

    k_build<<<BB, HH>>>(gids, lengths);
    cudaEventRecord(evBuild, 0);

    // side stream: w1 transpose (needed by mma0), then w2 transpose + base (needed by mma1)
    k_transpose<<<dim3(ND1 / 32, KD1 / 32), dim3(32, 8), 0, s1>>>(w1, w1t_p, KD1, ND1);
    cudaEventRecord(evT1, s1);
    k_transpose<<<dim3(ND2 / 32, ND1 / 32), dim3(32, 8), 0, s1>>>(w2, w2t_p, ND1, ND2);
    cudaStreamWaitEvent(s1, evBuild, 0);
    k_base<<<BB * SS * LL / 4, 128, 0, s1>>>(pos_emb, seq_emb, empty_tok, out, write_mask);
    cudaEventRecord(evSide, s1);

    // main stream
    k_gather_ln<<<MAXM, 128>>>(embed, tg_emb, gamma, beta, ht, pt, at, ct, tgap);
    cudaStreamWaitEvent(0, evT1, 0);
    k_mma0<<<dim3(ND1 / 128, MAXM / 128), 256, GS_BYTES>>>(w1t_p, b1);
    cudaStreamWaitEvent(0, evSide, 0);
    k_mma1<<<dim3(ND2 / 128, MAXM / 128, 2), 256, GS_BYTES>>>(w2t_p, b2, out);
}

// round 17
// speedup vs baseline: 1.0495x; 1.0092x over previous
#include <cuda_runtime.h>
#include <cuda_fp16.h>
#include <math.h>
#include <stdint.h>

// Problem constants
#define BB   32
#define LL   256
#define SS   4
#define DD   512
#define HH   1024      // L*S
#define TGBB 128
#define KD1  2560      // 5*D
#define ND1  2048      // 4*D
#define ND2  512       // D
#define MAXM (BB*HH)   // 32768

#define STATES_ELEMS ((size_t)BB*SS*LL*DD)   // 16777216
#define MASK_ELEMS   ((size_t)BB*SS*LL)      // 32768

// Scratch (device globals; no runtime allocation)
__device__ __align__(128) __half g_x[(size_t)MAXM * KD1];
__device__ __align__(128) __half g_h[(size_t)MAXM * ND1];
__device__ __align__(128) __half g_w1t[(size_t)ND1 * KD1];
__device__ __align__(128) __half g_w2t[(size_t)ND2 * ND1];
__device__ int   g_src[MAXM];
__device__ int   g_dst[MAXM];
__device__ int   g_count;
__device__ int   g_kept[BB * SS];
__device__ int   g_emptyf[BB * SS];

// ---------------------------------------------------------------------------
// Helpers
// ---------------------------------------------------------------------------
__device__ __forceinline__ uint32_t smem_u32(const void* p) {
    uint32_t a;
    asm("{ .reg .u64 t; cvta.to.shared.u64 t, %1; cvt.u32.u64 %0, t; }" : "=r"(a) : "l"(p));
    return a;
}
__device__ __forceinline__ void cpasync16(uint32_t dst, const void* src) {
    asm volatile("cp.async.cg.shared.global [%0], [%1], 16;\n" :: "r"(dst), "l"(src));
}
#define CP_COMMIT() asm volatile("cp.async.commit_group;\n" ::: "memory")
#define CP_WAIT2()  asm volatile("cp.async.wait_group 2;\n" ::: "memory")

__device__ __forceinline__ void mma_f16(float* c, const uint32_t* a, const uint32_t* b) {
    asm volatile(
        "mma.sync.aligned.m16n8k16.row.col.f32.f16.f16.f32 "
        "{%0,%1,%2,%3}, {%4,%5,%6,%7}, {%8,%9}, {%0,%1,%2,%3};"
        : "+f"(c[0]), "+f"(c[1]), "+f"(c[2]), "+f"(c[3])
        : "r"(a[0]), "r"(a[1]), "r"(a[2]), "r"(a[3]), "r"(b[0]), "r"(b[1]));
}
__device__ __forceinline__ void ldsm_x4(uint32_t* r, uint32_t addr) {
    asm volatile("ldmatrix.sync.aligned.m8n8.x4.shared.b16 {%0,%1,%2,%3}, [%4];"
        : "=r"(r[0]), "=r"(r[1]), "=r"(r[2]), "=r"(r[3]) : "r"(addr));
}
__device__ __forceinline__ float silu_fast(float x) {
    return x / (1.0f + __expf(-x));
}

// ---------------------------------------------------------------------------
// Per-batch bucketization
// ---------------------------------------------------------------------------
__global__ void k_build(const int* __restrict__ gids, const int* __restrict__ lengths) {
    int b = blockIdx.x;
    int h = threadIdx.x;
    int len = lengths[b];
    int g = (h < len) ? gids[b * HH + h] : 0;

    unsigned long long v = (g > 0) ? (1ULL << ((g - 1) * 16)) : 0ULL;
    int lane = h & 31, wid = h >> 5;
    #pragma unroll
    for (int o = 1; o < 32; o <<= 1) {
        unsigned long long n = __shfl_up_sync(0xffffffffu, v, o);
        if (lane >= o) v += n;
    }
    __shared__ unsigned long long warpsum[32];
    if (lane == 31) warpsum[wid] = v;
    __syncthreads();
    if (wid == 0) {
        unsigned long long w = warpsum[lane];
        #pragma unroll
        for (int o = 1; o < 32; o <<= 1) {
            unsigned long long n = __shfl_up_sync(0xffffffffu, w, o);
            if (lane >= o) w += n;
        }
        warpsum[lane] = w;
    }
    __syncthreads();
    unsigned long long incl = v + (wid > 0 ? warpsum[wid - 1] : 0ULL);

    __shared__ unsigned long long s_total;
    if (h == HH - 1) s_total = incl;
    __syncthreads();
    unsigned long long tot = s_total;

    if (g > 0) {
        int rank0 = (int)((incl >> ((g - 1) * 16)) & 0xFFFF) - 1;
        int cnt   = (int)((tot  >> ((g - 1) * 16)) & 0xFFFF);
        int off = cnt - LL; if (off < 0) off = 0;
        if (rank0 >= off) {
            int m = atomicAdd(&g_count, 1);
            g_src[m] = b * HH + h;
            g_dst[m] = (b * SS + (g - 1)) * LL + (rank0 - off);
        }
    }
    if (h < SS) {
        int cnt = (int)((tot >> (h * 16)) & 0xFFFF);
        int kept = (cnt == 0) ? 1 : (cnt < LL ? cnt : LL);
        g_kept[b * SS + h] = kept;
        g_emptyf[b * SS + h] = (cnt == 0) ? 1 : 0;
    }
}

// ---------------------------------------------------------------------------
// Output base init + mask: 128 threads, 4 consecutive rows per block
// ---------------------------------------------------------------------------
__global__ void k_base(const float* __restrict__ pos_emb, const float* __restrict__ seq_emb,
                       const float* __restrict__ empty_tok, float* __restrict__ out,
                       int write_mask) {
    int tid = threadIdx.x;
    int r0 = blockIdx.x * 4;
    #pragma unroll
    for (int q = 0; q < 4; q++) {
        int r = r0 + q;
        int slot = r & (LL - 1);
        int bg = r >> 8;
        int g = bg & (SS - 1);
        int kept = g_kept[bg];

        float4 val = make_float4(0.f, 0.f, 0.f, 0.f);
        if (slot < kept) {
            float4 a = ((const float4*)(pos_emb + (size_t)slot * DD))[tid];
            float4 qv = ((const float4*)(seq_emb + (size_t)(g + 1) * DD))[tid];
            val.x = a.x + qv.x; val.y = a.y + qv.y; val.z = a.z + qv.z; val.w = a.w + qv.w;
            if (slot == 0 && g_emptyf[bg]) {
                float4 e = ((const float4*)(empty_tok + (size_t)g * DD))[tid];
                val.x += e.x; val.y += e.y; val.z += e.z; val.w += e.w;
            }
        }
        ((float4*)out)[(size_t)r * (DD / 4) + tid] = val;
        if (write_mask && tid == 0)
            out[STATES_ELEMS + r] = (slot < kept) ? 1.0f : 0.0f;
    }
}

// ---------------------------------------------------------------------------
// Weight transpose [K,N] -> [N,K], fp16 output
// ---------------------------------------------------------------------------
__global__ void k_transpose(const float* __restrict__ W, __half* __restrict__ Wt, int K, int N) {
    __shared__ float t[32][33];
    int n0 = blockIdx.x * 32, k0 = blockIdx.y * 32;
    int tx = threadIdx.x, ty = threadIdx.y;   // 32 x 8
    #pragma unroll
    for (int j = 0; j < 32; j += 8)
        t[ty + j][tx] = W[(size_t)(k0 + ty + j) * N + n0 + tx];
    __syncthreads();
    #pragma unroll
    for (int j = 0; j < 32; j += 8)
        Wt[(size_t)(n0 + ty + j) * K + k0 + tx] = __float2half_rn(t[tx][ty + j]);
}

// ---------------------------------------------------------------------------
// Gather 5 embeddings + LayerNorm: warp-per-row, no smem, no __syncthreads.
// 256 threads = 8 warps; warp w handles row blockIdx.x*8 + w.
// Lane covers 8 consecutive floats per step; 10 steps x 256 floats = 2560.
// ---------------------------------------------------------------------------
__global__ void __launch_bounds__(256)
k_gather_ln(const float* __restrict__ embed, const float* __restrict__ tg_emb,
            const float* __restrict__ gamma, const float* __restrict__ beta,
            const int* __restrict__ ht, const int* __restrict__ pt,
            const int* __restrict__ at, const int* __restrict__ ct,
            const int* __restrict__ tgap) {
    int lane = threadIdx.x & 31;
    int row = blockIdx.x * 8 + (threadIdx.x >> 5);
    if (row >= g_count) return;

    int src = g_src[row];
    const float* segs[5];
    segs[0] = embed + (size_t)ht[src] * DD;
    segs[1] = embed + (size_t)pt[src] * DD;
    segs[2] = embed + (size_t)at[src] * DD;
    segs[3] = embed + (size_t)ct[src] * DD;
    int tg = tgap[src];
    tg = tg < 0 ? 0 : (tg > TGBB ? TGBB : tg);
    segs[4] = tg_emb + (size_t)tg * DD;

    // pass 1: sums (each lane: 8 consecutive floats per step)
    float s = 0.f, ss = 0.f;
    #pragma unroll
    for (int c = 0; c < 10; c++) {
        const float* sp = segs[c >> 1] + (c & 1) * 256 + lane * 8;
        float4 a = *(const float4*)sp;
        float4 b = *(const float4*)(sp + 4);
        s  += a.x + a.y + a.z + a.w + b.x + b.y + b.z + b.w;
        ss += a.x * a.x + a.y * a.y + a.z * a.z + a.w * a.w
            + b.x * b.x + b.y * b.y + b.z * b.z + b.w * b.w;
    }
    #pragma unroll
    for (int o = 16; o > 0; o >>= 1) {
        s  += __shfl_down_sync(0xffffffffu, s,  o);
        ss += __shfl_down_sync(0xffffffffu, ss, o);
    }
    s  = __shfl_sync(0xffffffffu, s, 0);
    ss = __shfl_sync(0xffffffffu, ss, 0);
    float mean = s * (1.0f / (float)KD1);
    float var  = ss * (1.0f / (float)KD1) - mean * mean;
    float rstd = rsqrtf(var + 1e-5f);

    // pass 2: reload (L1-hot), normalize, store 16B per step
    size_t base = (size_t)row * KD1;
    #pragma unroll
    for (int c = 0; c < 10; c++) {
        int j = c * 256 + lane * 8;
        const float* sp = segs[c >> 1] + (c & 1) * 256 + lane * 8;
        float4 a = *(const float4*)sp;
        float4 b = *(const float4*)(sp + 4);
        float4 g0 = *(const float4*)(gamma + j);
        float4 g1 = *(const float4*)(gamma + j + 4);
        float4 b0 = *(const float4*)(beta + j);
        float4 b1 = *(const float4*)(beta + j + 4);
        half2 h0 = __floats2half2_rn((a.x - mean) * rstd * g0.x + b0.x,
                                     (a.y - mean) * rstd * g0.y + b0.y);
        half2 h1 = __floats2half2_rn((a.z - mean) * rstd * g0.z + b0.z,
                                     (a.w - mean) * rstd * g0.w + b0.w);
        half2 h2 = __floats2half2_rn((b.x - mean) * rstd * g1.x + b1.x,
                                     (b.y - mean) * rstd * g1.y + b1.y);
        half2 h3 = __floats2half2_rn((b.z - mean) * rstd * g1.z + b1.z,
                                     (b.w - mean) * rstd * g1.w + b1.w);
        uint4 pk = make_uint4(*(uint32_t*)&h0, *(uint32_t*)&h1,
                              *(uint32_t*)&h2, *(uint32_t*)&h3);
        *(uint4*)&g_x[base + j] = pk;
    }
}

// ---------------------------------------------------------------------------
// FP16 mma.sync GEMM: CTA tile 128x128, K-chunk 64, 3-stage cp.async,
// ldmatrix.x4 fragments, row pitch 72 halves (conflict-free).
// ---------------------------------------------------------------------------
#define ROWP      72
#define ROWB      (ROWP * 2)                // 144 bytes
#define TILE_A    (128 * ROWB)              // 18432
#define STG       (TILE_A * 2)              // 36864
#define GS_BYTES  (3 * STG)                 // 110592

// GEMM1: g_h = fp16(silu(g_x @ w1 + b1))   K=2560, N=2048
__global__ void __launch_bounds__(256, 2)
k_mma0(const __half* __restrict__ Bt, const float* __restrict__ bias) {
    constexpr int K  = KD1;
    constexpr int NC = K / 64;

    const int count = g_count;
    const int m0 = blockIdx.y * 128;
    if (m0 >= count) return;
    const int n0 = blockIdx.x * 128;

    extern __shared__ __align__(16) char smc[];
    const uint32_t sb = smem_u32(smc);
    const int tid = threadIdx.x;
    const int wid = tid >> 5, lane = tid & 31;
    const int wm = wid & 1, wn = wid >> 1;
    const int g = lane >> 2, tig = lane & 3;
    const int mclamp = count - 1;

    const uint32_t aLane = (uint32_t)(lane & 15) * ROWB + ((lane >> 4) << 3) * 2;
    const uint32_t bLane = (uint32_t)(((lane >> 4) << 3) + (lane & 7)) * ROWB
                         + (((lane >> 3) & 1) << 3) * 2;

    float acc[4][4][4];
    #pragma unroll
    for (int mt = 0; mt < 4; mt++)
        #pragma unroll
        for (int nt = 0; nt < 4; nt++)
            #pragma unroll
            for (int q = 0; q < 4; q++) acc[mt][nt][q] = 0.f;

    auto load_chunk = [&](int c, int st) {
        int kc = c * 64;
        uint32_t aB = sb + st * STG;
        uint32_t bB = aB + TILE_A;
        int id = tid;
        #pragma unroll
        for (int j = 0; j < 4; j++) {
            int r = id >> 3, cc = id & 7;
            int gr = m0 + r; gr = gr > mclamp ? mclamp : gr;
            cpasync16(aB + r * ROWB + cc * 16, g_x + (size_t)gr * K + kc + cc * 8);
            id += 256;
        }
        id = tid;
        #pragma unroll
        for (int j = 0; j < 4; j++) {
            int r = id >> 3, cc = id & 7;
            cpasync16(bB + r * ROWB + cc * 16, Bt + (size_t)(n0 + r) * K + kc + cc * 8);
            id += 256;
        }
    };

    #pragma unroll
    for (int c = 0; c < 3; c++) { load_chunk(c, c); CP_COMMIT(); }

    int stage = 0;
    for (int i = 0; i < NC; i++) {
        CP_WAIT2();
        __syncthreads();

        uint32_t aS = sb + stage * STG;
        uint32_t bS = aS + TILE_A;

        #pragma unroll
        for (int ks = 0; ks < 4; ks++) {
            uint32_t kOff = ks * 32;
            uint32_t afr[4][4];
            uint32_t bfr[2][4];
            #pragma unroll
            for (int mt = 0; mt < 4; mt++)
                ldsm_x4(afr[mt], aS + (uint32_t)(wm * 64 + mt * 16) * ROWB + aLane + kOff);
            #pragma unroll
            for (int p = 0; p < 2; p++)
                ldsm_x4(bfr[p], bS + (uint32_t)(wn * 32 + p * 16) * ROWB + bLane + kOff);
            #pragma unroll
            for (int mt = 0; mt < 4; mt++) {
                #pragma unroll
                for (int p = 0; p < 2; p++) {
                    mma_f16(acc[mt][2 * p],     afr[mt], &bfr[p][0]);
                    mma_f16(acc[mt][2 * p + 1], afr[mt], &bfr[p][2]);
                }
            }
        }
        __syncthreads();
        if (i + 3 < NC) load_chunk(i + 3, stage);
        CP_COMMIT();
        stage = (stage == 2) ? 0 : stage + 1;
    }

    #pragma unroll
    for (int mt = 0; mt < 4; mt++) {
        int r1 = m0 + wm * 64 + mt * 16 + g;
        int r2 = r1 + 8;
        bool v1 = r1 < count, v2 = r2 < count;
        #pragma unroll
        for (int nt = 0; nt < 4; nt++) {
            int c = n0 + wn * 32 + nt * 8 + tig * 2;
            float bx = __ldg(&bias[c]), by = __ldg(&bias[c + 1]);
            if (v1) {
                float x = silu_fast(acc[mt][nt][0] + bx);
                float y = silu_fast(acc[mt][nt][1] + by);
                *(half2*)&g_h[(size_t)r1 * ND1 + c] = __floats2half2_rn(x, y);
            }
            if (v2) {
                float x = silu_fast(acc[mt][nt][2] + bx);
                float y = silu_fast(acc[mt][nt][3] + by);
                *(half2*)&g_h[(size_t)r2 * ND1 + c] = __floats2half2_rn(x, y);
            }
        }
    }
}

// GEMM2 split-K=2: out[g_dst[m]] += (g_h @ w2)[k-half] (+ b2 on z==0), via atomicAdd.
__global__ void __launch_bounds__(256, 2)
k_mma1(const __half* __restrict__ Bt, const float* __restrict__ bias, float* __restrict__ out) {
    constexpr int KH = ND1 / 2;      // 1024 per K-half
    constexpr int NC = KH / 64;      // 16 chunks

    const int count = g_count;
    const int m0 = blockIdx.y * 128;
    if (m0 >= count) return;
    const int n0 = blockIdx.x * 128;
    const int kbase = blockIdx.z * KH;
    const bool addBias = (blockIdx.z == 0);

    extern __shared__ __align__(16) char smc[];
    const uint32_t sb = smem_u32(smc);
    const int tid = threadIdx.x;
    const int wid = tid >> 5, lane = tid & 31;
    const int wm = wid & 1, wn = wid >> 1;
    const int g = lane >> 2, tig = lane & 3;
    const int mclamp = count - 1;

    const uint32_t aLane = (uint32_t)(lane & 15) * ROWB + ((lane >> 4) << 3) * 2;
    const uint32_t bLane = (uint32_t)(((lane >> 4) << 3) + (lane & 7)) * ROWB
                         + (((lane >> 3) & 1) << 3) * 2;

    float acc[4][4][4];
    #pragma unroll
    for (int mt = 0; mt < 4; mt++)
        #pragma unroll
        for (int nt = 0; nt < 4; nt++)
            #pragma unroll
            for (int q = 0; q < 4; q++) acc[mt][nt][q] = 0.f;

    auto load_chunk = [&](int c, int st) {
        int kc = kbase + c * 64;
        uint32_t aB = sb + st * STG;
        uint32_t bB = aB + TILE_A;
        int id = tid;
        #pragma unroll
        for (int j = 0; j < 4; j++) {
            int r = id >> 3, cc = id & 7;
            int gr = m0 + r; gr = gr > mclamp ? mclamp : gr;
            cpasync16(aB + r * ROWB + cc * 16, g_h + (size_t)gr * ND1 + kc + cc * 8);
            id += 256;
        }
        id = tid;
        #pragma unroll
        for (int j = 0; j < 4; j++) {
            int r = id >> 3, cc = id & 7;
            cpasync16(bB + r * ROWB + cc * 16, Bt + (size_t)(n0 + r) * ND1 + kc + cc * 8);
            id += 256;
        }
    };

    #pragma unroll
    for (int c = 0; c < 3; c++) { load_chunk(c, c); CP_COMMIT(); }

    int stage = 0;
    for (int i = 0; i < NC; i++) {
        CP_WAIT2();
        __syncthreads();

        uint32_t aS = sb + stage * STG;
        uint32_t bS = aS + TILE_A;

        #pragma unroll
        for (int ks = 0; ks < 4; ks++) {
            uint32_t kOff = ks * 32;
            uint32_t afr[4][4];
            uint32_t bfr[2][4];
            #pragma unroll
            for (int mt = 0; mt < 4; mt++)
                ldsm_x4(afr[mt], aS + (uint32_t)(wm * 64 + mt * 16) * ROWB + aLane + kOff);
            #pragma unroll
            for (int p = 0; p < 2; p++)
                ldsm_x4(bfr[p], bS + (uint32_t)(wn * 32 + p * 16) * ROWB + bLane + kOff);
            #pragma unroll
            for (int mt = 0; mt < 4; mt++) {
                #pragma unroll
                for (int p = 0; p < 2; p++) {
                    mma_f16(acc[mt][2 * p],     afr[mt], &bfr[p][0]);
                    mma_f16(acc[mt][2 * p + 1], afr[mt], &bfr[p][2]);
                }
            }
        }
        __syncthreads();
        if (i + 3 < NC) load_chunk(i + 3, stage);
        CP_COMMIT();
        stage = (stage == 2) ? 0 : stage + 1;
    }

    // ---- epilogue: atomic scatter accumulate ----
    #pragma unroll
    for (int mt = 0; mt < 4; mt++) {
        int r1 = m0 + wm * 64 + mt * 16 + g;
        int r2 = r1 + 8;
        bool v1 = r1 < count, v2 = r2 < count;
        int d1 = v1 ? g_dst[r1] : 0;
        int d2 = v2 ? g_dst[r2] : 0;
        #pragma unroll
        for (int nt = 0; nt < 4; nt++) {
            int c = n0 + wn * 32 + nt * 8 + tig * 2;
            float bx = addBias ? __ldg(&bias[c]) : 0.f;
            float by = addBias ? __ldg(&bias[c + 1]) : 0.f;
            if (v1) {
                float* p = &out[(size_t)d1 * ND2 + c];
                atomicAdd(p,     acc[mt][nt][0] + bx);
                atomicAdd(p + 1, acc[mt][nt][1] + by);
            }
            if (v2) {
                float* p = &out[(size_t)d2 * ND2 + c];
                atomicAdd(p,     acc[mt][nt][2] + bx);
                atomicAdd(p + 1, acc[mt][nt][3] + by);
            }
        }
    }
}

// ---------------------------------------------------------------------------
extern "C" void kernel_launch(void* const* d_in, const int* in_sizes, int n_in,
                              void* d_out, int out_size) {
    const float* embed     = (const float*)d_in[0];
    const float* tg_emb    = (const float*)d_in[1];
    const float* seq_emb   = (const float*)d_in[2];
    const float* pos_emb   = (const float*)d_in[3];
    const float* gamma     = (const float*)d_in[4];
    const float* beta      = (const float*)d_in[5];
    const float* w1        = (const float*)d_in[6];
    const float* b1        = (const float*)d_in[7];
    const float* w2        = (const float*)d_in[8];
    const float* b2        = (const float*)d_in[9];
    const float* empty_tok = (const float*)d_in[10];
    const int*   ht        = (const int*)d_in[11];
    const int*   pt        = (const int*)d_in[12];
    const int*   at        = (const int*)d_in[13];
    const int*   ct        = (const int*)d_in[14];
    const int*   tgap      = (const int*)d_in[15];
    const int*   gids      = (const int*)d_in[16];
    const int*   lengths   = (const int*)d_in[17];
    float* out = (float*)d_out;

    int write_mask = ((size_t)out_size >= STATES_ELEMS + MASK_ELEMS) ? 1 : 0;

    __half* w1t_p; cudaGetSymbolAddress((void**)&w1t_p, g_w1t);
    __half* w2t_p; cudaGetSymbolAddress((void**)&w2t_p, g_w2t);
    int* cnt_p;    cudaGetSymbolAddress((void**)&cnt_p, g_count);

    static cudaStream_t s1 = nullptr;
    static cudaEvent_t evFork = nullptr, evBuild = nullptr, evT1 = nullptr, evSide = nullptr;
    if (!s1) {
        cudaStreamCreateWithFlags(&s1, cudaStreamNonBlocking);
        cudaEventCreateWithFlags(&evFork,  cudaEventDisableTiming);
        cudaEventCreateWithFlags(&evBuild, cudaEventDisableTiming);
        cudaEventCreateWithFlags(&evT1,    cudaEventDisableTiming);
        cudaEventCreateWithFlags(&evSide,  cudaEventDisableTiming);
    }

    cudaFuncSetAttribute(k_mma0, cudaFuncAttributeMaxDynamicSharedMemorySize, GS_BYTES);
    cudaFuncSetAttribute(k_mma1, cudaFuncAttributeMaxDynamicSharedMemorySize, GS_BYTES);

    cudaMemsetAsync(cnt_p, 0, sizeof(int), 0);
    cudaEventRecord(evFork, 0);
    cudaStreamWaitEvent(s1, evFork, 0);

    k_build<<<BB, HH>>>(gids, lengths);
    cudaEventRecord(evBuild, 0);

    // side stream: w1 transpose (needed by mma0), then w2 transpose + base (needed by mma1)
    k_transpose<<<dim3(ND1 / 32, KD1 / 32), dim3(32, 8), 0, s1>>>(w1, w1t_p, KD1, ND1);
    cudaEventRecord(evT1, s1);
    k_transpose<<<dim3(ND2 / 32, ND1 / 32), dim3(32, 8), 0, s1>>>(w2, w2t_p, ND1, ND2);
    cudaStreamWaitEvent(s1, evBuild, 0);
    k_base<<<BB * SS * LL / 4, 128, 0, s1>>>(pos_emb, seq_emb, empty_tok, out, write_mask);
    cudaEventRecord(evSide, s1);

    // main stream
    k_gather_ln<<<MAXM / 8, 256>>>(embed, tg_emb, gamma, beta, ht, pt, at, ct, tgap);
    cudaStreamWaitEvent(0, evT1, 0);
    k_mma0<<<dim3(ND1 / 128, MAXM / 128), 256, GS_BYTES>>>(w1t_p, b1);
    cudaStreamWaitEvent(0, evSide, 0);
    k_mma1<<<dim3(ND2 / 128, MAXM / 128, 2), 256, GS_BYTES>>>(w2t_p, b2, out);
}